// round 12
// baseline (speedup 1.0000x reference)
#include <cuda_runtime.h>
#include <stdint.h>

// out[n] = image[pixel*3 + perm[n]], perm in {0,1,2} per element.
// 8 pixels per thread = 24 elements = 6 x float4 (img) + 6 x int4 (perm)
// + 6 x float4 (out). All loads/stores use .cs (streaming / evict-first)
// since every byte is touched exactly once — keeps L2 from thrashing on
// three 201MB single-pass streams.
//
// Channel select is positional ternaries -> ISETP/SEL in registers,
// no dynamic register indexing (no local-memory spill).

static __device__ __forceinline__ float sel3(int p, float a, float b, float c) {
    return (p == 0) ? a : ((p == 1) ? b : c);
}

// Permute one group of 4 pixels given 3 img float4s and 3 perm int4s.
static __device__ __forceinline__ void perm_quad(
    const float4& v0, const float4& v1, const float4& v2,
    const int4&   q0, const int4&   q1, const int4&   q2,
    float4& o0, float4& o1, float4& o2)
{
    // Pixel 0: (v0.x v0.y v0.z)   Pixel 1: (v0.w v1.x v1.y)
    // Pixel 2: (v1.z v1.w v2.x)   Pixel 3: (v2.y v2.z v2.w)
    o0.x = sel3(q0.x, v0.x, v0.y, v0.z);
    o0.y = sel3(q0.y, v0.x, v0.y, v0.z);
    o0.z = sel3(q0.z, v0.x, v0.y, v0.z);
    o0.w = sel3(q0.w, v0.w, v1.x, v1.y);

    o1.x = sel3(q1.x, v0.w, v1.x, v1.y);
    o1.y = sel3(q1.y, v0.w, v1.x, v1.y);
    o1.z = sel3(q1.z, v1.z, v1.w, v2.x);
    o1.w = sel3(q1.w, v1.z, v1.w, v2.x);

    o2.x = sel3(q2.x, v1.z, v1.w, v2.x);
    o2.y = sel3(q2.y, v2.y, v2.z, v2.w);
    o2.z = sel3(q2.z, v2.y, v2.z, v2.w);
    o2.w = sel3(q2.w, v2.y, v2.z, v2.w);
}

__global__ void __launch_bounds__(256)
perpixel_perm_kernel(const float4* __restrict__ img4,
                     const int4*   __restrict__ prm4,
                     float4*       __restrict__ out4,
                     int n_octs /* number of 8-pixel groups */) {
    int t = blockIdx.x * blockDim.x + threadIdx.x;
    if (t >= n_octs) return;

    const int base = t * 6;

    // Front-batched streaming loads: 12 independent LDG.128 (MLP_p1 = 12)
    float4 v0 = __ldcs(&img4[base + 0]);
    float4 v1 = __ldcs(&img4[base + 1]);
    float4 v2 = __ldcs(&img4[base + 2]);
    float4 v3 = __ldcs(&img4[base + 3]);
    float4 v4 = __ldcs(&img4[base + 4]);
    float4 v5 = __ldcs(&img4[base + 5]);

    int4 q0 = __ldcs(&prm4[base + 0]);
    int4 q1 = __ldcs(&prm4[base + 1]);
    int4 q2 = __ldcs(&prm4[base + 2]);
    int4 q3 = __ldcs(&prm4[base + 3]);
    int4 q4 = __ldcs(&prm4[base + 4]);
    int4 q5 = __ldcs(&prm4[base + 5]);

    float4 o0, o1, o2, o3, o4, o5;
    perm_quad(v0, v1, v2, q0, q1, q2, o0, o1, o2);
    perm_quad(v3, v4, v5, q3, q4, q5, o3, o4, o5);

    __stcs(&out4[base + 0], o0);
    __stcs(&out4[base + 1], o1);
    __stcs(&out4[base + 2], o2);
    __stcs(&out4[base + 3], o3);
    __stcs(&out4[base + 4], o4);
    __stcs(&out4[base + 5], o5);
}

extern "C" void kernel_launch(void* const* d_in, const int* in_sizes, int n_in,
                              void* d_out, int out_size) {
    const float* image = (const float*)d_in[0];
    const int*   perm  = (const int*)d_in[1];
    float*       out   = (float*)d_out;

    const int n_elems = in_sizes[0];   // 4096*4096*3 = 50331648, divisible by 24
    const int n_octs  = n_elems / 24;  // 2,097,152 threads

    const int threads = 256;
    const int blocks  = (n_octs + threads - 1) / threads;  // 8192 blocks

    perpixel_perm_kernel<<<blocks, threads>>>(
        (const float4*)image, (const int4*)perm, (float4*)out, n_octs);
}

// round 13
// speedup vs baseline: 1.0568x; 1.0568x over previous
#include <cuda_runtime.h>
#include <stdint.h>

// out[n] = image[pixel*3 + perm[n]], perm in {0,1,2} per element.
//
// Proven-best shape (R5): 4 pixels per thread = 12 elements =
// 3 x float4 (img) + 3 x int4 (perm) + 3 x float4 (out).
// Plain cached loads (__ldg) and normal stores — the .cs streaming
// variant doubled L2 transactions per DRAM byte and regressed.
// Channel select is positional ternaries -> ISETP/SEL in registers,
// no dynamic register indexing (no local-memory spill).

static __device__ __forceinline__ float sel3(int p, float a, float b, float c) {
    // p in {0,1,2}
    return (p == 0) ? a : ((p == 1) ? b : c);
}

__global__ void __launch_bounds__(512)
perpixel_perm_kernel(const float4* __restrict__ img4,
                     const int4*   __restrict__ prm4,
                     float4*       __restrict__ out4,
                     int n_quads /* number of 4-pixel groups */) {
    int t = blockIdx.x * blockDim.x + threadIdx.x;
    if (t >= n_quads) return;

    const int base = t * 3;

    // 12 image floats covering 4 pixels (front-batched LDG.128, MLP_p1 = 6)
    float4 v0 = __ldg(&img4[base + 0]);
    float4 v1 = __ldg(&img4[base + 1]);
    float4 v2 = __ldg(&img4[base + 2]);

    // 12 perm ints covering 4 pixels
    int4 q0 = __ldg(&prm4[base + 0]);
    int4 q1 = __ldg(&prm4[base + 1]);
    int4 q2 = __ldg(&prm4[base + 2]);

    // Pixel 0: channels (v0.x, v0.y, v0.z), perms (q0.x, q0.y, q0.z)
    // Pixel 1: channels (v0.w, v1.x, v1.y), perms (q0.w, q1.x, q1.y)
    // Pixel 2: channels (v1.z, v1.w, v2.x), perms (q1.z, q1.w, q2.x)
    // Pixel 3: channels (v2.y, v2.z, v2.w), perms (q2.y, q2.z, q2.w)

    float4 o0, o1, o2;

    o0.x = sel3(q0.x, v0.x, v0.y, v0.z);
    o0.y = sel3(q0.y, v0.x, v0.y, v0.z);
    o0.z = sel3(q0.z, v0.x, v0.y, v0.z);
    o0.w = sel3(q0.w, v0.w, v1.x, v1.y);

    o1.x = sel3(q1.x, v0.w, v1.x, v1.y);
    o1.y = sel3(q1.y, v0.w, v1.x, v1.y);
    o1.z = sel3(q1.z, v1.z, v1.w, v2.x);
    o1.w = sel3(q1.w, v1.z, v1.w, v2.x);

    o2.x = sel3(q2.x, v1.z, v1.w, v2.x);
    o2.y = sel3(q2.y, v2.y, v2.z, v2.w);
    o2.z = sel3(q2.z, v2.y, v2.z, v2.w);
    o2.w = sel3(q2.w, v2.y, v2.z, v2.w);

    out4[base + 0] = o0;
    out4[base + 1] = o1;
    out4[base + 2] = o2;
}

extern "C" void kernel_launch(void* const* d_in, const int* in_sizes, int n_in,
                              void* d_out, int out_size) {
    const float* image = (const float*)d_in[0];
    const int*   perm  = (const int*)d_in[1];
    float*       out   = (float*)d_out;

    const int n_elems = in_sizes[0];       // 4096*4096*3 = 50331648, divisible by 12
    const int n_quads = n_elems / 12;      // 4,194,304 threads

    const int threads = 512;
    const int blocks  = (n_quads + threads - 1) / threads;  // 8192 blocks

    perpixel_perm_kernel<<<blocks, threads>>>(
        (const float4*)image, (const int4*)perm, (float4*)out, n_quads);
}